// round 12
// baseline (speedup 1.0000x reference)
#include <cuda_runtime.h>
#include <math.h>
#include <stdint.h>

// Problem constants
#define Bc   256
#define Mc   196
#define Dc   512
#define TRIc 131328           // 512*513/2
#define TB   128              // output tile (TB x TB)
#define KP   224              // padded token count (7 * 32)
#define KCH  32               // K per chunk
#define NCHK 7
#define NPAIR 10
#define TILEB 4096            // 128 rows * 32 bytes
#define STAGEB (4 * TILEB)    // Aa,Ab,Ba,Bb = 16384

// Scratch (allocation-free rule: __device__ globals)
__device__ float  g_diag[Bc * Dc];
__device__ float  g_rowsum[Bc * Dc];
__device__ int8_t g_qa[(size_t)Bc * Dc * KP];   // level-1 int8, [b][feat][tok]
__device__ int8_t g_qb[(size_t)Bc * Dc * KP];   // level-2 residual int8

__constant__ int c_bi[NPAIR] = {0,0,0,0,1,1,1,2,2,3};
__constant__ int c_bj[NPAIR] = {0,1,2,3,1,2,3,2,3,3};

// ---------------------------------------------------------------------------
// PTX helpers (base PTX: ldmatrix / mma.sync s8 / cp.async — sm_103-safe)
// ---------------------------------------------------------------------------
__device__ __forceinline__ void ldm4(uint32_t& r0, uint32_t& r1, uint32_t& r2,
                                     uint32_t& r3, uint32_t addr) {
    asm volatile("ldmatrix.sync.aligned.m8n8.x4.shared.b16 {%0,%1,%2,%3}, [%4];"
                 : "=r"(r0), "=r"(r1), "=r"(r2), "=r"(r3) : "r"(addr));
}

__device__ __forceinline__ void mma_s8(int* d, const uint32_t* a,
                                       uint32_t b0, uint32_t b1) {
    asm volatile(
        "mma.sync.aligned.m16n8k32.row.col.s32.s8.s8.s32 "
        "{%0,%1,%2,%3}, {%4,%5,%6,%7}, {%8,%9}, {%0,%1,%2,%3};"
        : "+r"(d[0]), "+r"(d[1]), "+r"(d[2]), "+r"(d[3])
        : "r"(a[0]), "r"(a[1]), "r"(a[2]), "r"(a[3]), "r"(b0), "r"(b1));
}

__device__ __forceinline__ void cp16(uint32_t saddr, const void* gaddr) {
    asm volatile("cp.async.ca.shared.global [%0], [%1], 16;"
                 :: "r"(saddr), "l"(gaddr) : "memory");
}
__device__ __forceinline__ void cp_commit() {
    asm volatile("cp.async.commit_group;" ::: "memory");
}
template<int N>
__device__ __forceinline__ void cp_wait() {
    asm volatile("cp.async.wait_group %0;" :: "n"(N) : "memory");
}

// swizzled address within a [128 rows][32B] tile: 16B half h of row, XOR'd by
// bit2 of the row so 8-row ldmatrix phases hit 8 distinct banks.
__device__ __forceinline__ uint32_t qaddr(uint32_t tilebase, int row, int h) {
    return tilebase + (uint32_t)(row * 32) + ((uint32_t)(h ^ ((row >> 2) & 1)) << 4);
}

// ---------------------------------------------------------------------------
// Kernel 0: quantize + transpose.  x[b][tok][feat] fp32 ->
// g_qa/g_qb[b][feat][tok(224 padded)] int8.   16x = a + b/254 + eps.
// grid (KP/16, Dc/64, Bc), 256 thr; tile = 16 tokens x 64 features.
// ---------------------------------------------------------------------------
__global__ void __launch_bounds__(256) quant_kernel(const float* __restrict__ x) {
    __shared__ float tile[16][68];
    const int k0 = blockIdx.x * 16;
    const int f0 = blockIdx.y * 64;
    const int b  = blockIdx.z;
    const int t  = threadIdx.x;
    {
        const int kk = t >> 4, ff = (t & 15) << 2;
        const int kg = k0 + kk;
        float4 v = make_float4(0.f, 0.f, 0.f, 0.f);
        if (kg < Mc)
            v = *(const float4*)(x + ((size_t)b * Mc + kg) * Dc + f0 + ff);
        tile[kk][ff] = v.x; tile[kk][ff + 1] = v.y;
        tile[kk][ff + 2] = v.z; tile[kk][ff + 3] = v.w;
    }
    __syncthreads();
    {
        const int f = t >> 2, kq = (t & 3) << 2;
        uint32_t pa = 0, pb = 0;
#pragma unroll
        for (int u = 0; u < 4; ++u) {
            const float vs = tile[kq + u][f] * 16.f;
            int a = __float2int_rn(vs);
            a = max(-127, min(127, a));
            int bq = __float2int_rn((vs - (float)a) * 254.f);
            bq = max(-127, min(127, bq));
            pa |= ((uint32_t)(uint8_t)(int8_t)a)  << (u * 8);
            pb |= ((uint32_t)(uint8_t)(int8_t)bq) << (u * 8);
        }
        const size_t off = ((size_t)b * Dc + f0 + f) * KP + k0 + kq;
        *(uint32_t*)(g_qa + off) = pa;
        *(uint32_t*)(g_qb + off) = pb;
    }
}

// ---------------------------------------------------------------------------
// Kernel 1: diag[b,d] = sum_m x[b,m,d]^2   (fp32, exact)
// ---------------------------------------------------------------------------
__global__ void __launch_bounds__(512) diag_kernel(const float* __restrict__ x) {
    int b = blockIdx.x;
    int d = threadIdx.x;
    const float* xb = x + (size_t)b * Mc * Dc + d;
    float s = 0.f;
#pragma unroll 4
    for (int m = 0; m < Mc; ++m) {
        float v = xb[(size_t)m * Dc];
        s = fmaf(v, v, s);
    }
    g_diag[b * Dc + d] = s;
}

// ---------------------------------------------------------------------------
// Kernel 2: zero g_rowsum
// ---------------------------------------------------------------------------
__global__ void __launch_bounds__(512) zero_kernel() {
    g_rowsum[blockIdx.x * 512 + threadIdx.x] = 0.f;
}

// ---------------------------------------------------------------------------
// Kernel 3: 128x128 gram tile via int8 two-level mma.sync m16n8k32,
// cp.async double-buffered.  gram = aa/256 + (ab+ba)/65024  (bb dropped).
// 256 threads = 8 warps; warp tile 32(M) x 64(N).
// STATIC smem: 2 stages x [Aa|Ab|Ba|Bb] (128 x 32B, XOR swizzle) = 32KB.
// ---------------------------------------------------------------------------
__global__ void __launch_bounds__(256, 2) gram_kernel(const float* __restrict__ t,
                                                      float* __restrict__ out) {
    __shared__ __align__(16) char smem[2 * STAGEB];
    __shared__ float rsum_i[TB];
    __shared__ float rsum_j[TB];
    const uint32_t sbase = (uint32_t)__cvta_generic_to_shared(smem);

    const int b   = blockIdx.y;
    const int bi  = c_bi[blockIdx.x];
    const int bj  = c_bj[blockIdx.x];
    const int tid = threadIdx.x;
    const int lane = tid & 31;
    const int wid  = tid >> 5;
    const int wm   = wid & 3;    // M group (32 rows)
    const int wn   = wid >> 2;   // N half (64 cols)

    const size_t bbase = (size_t)b * Dc * KP;
    const int i0 = bi * TB, j0 = bj * TB;

    // cp.async: 1024 16B-chunks per stage over 256 threads (4 each)
    // slot -> tile(2b) | row(7b) | half(1b)
    auto issue_chunk = [&](int ch, int st) {
        const uint32_t stb = sbase + st * STAGEB;
        const int k0c = ch * KCH;
#pragma unroll
        for (int it = 0; it < 4; ++it) {
            const int slot  = tid + it * 256;
            const int tile  = slot >> 8;
            const int inner = slot & 255;
            const int r     = inner >> 1;
            const int h     = inner & 1;
            const int8_t* bp = (tile & 1) ? g_qb : g_qa;
            const int rowoff = (tile >> 1) ? j0 : i0;
            const int8_t* src = bp + bbase + (size_t)(rowoff + r) * KP + k0c + h * 16;
            cp16(qaddr(stb + tile * TILEB, r, h), src);
        }
        cp_commit();
    };

    if (tid < TB) { rsum_i[tid] = 0.f; rsum_j[tid] = 0.f; }

    int acc_aa[2][8][4];
    int acc_m [2][8][4];
#pragma unroll
    for (int mt = 0; mt < 2; ++mt)
#pragma unroll
        for (int nt = 0; nt < 8; ++nt)
#pragma unroll
            for (int v = 0; v < 4; ++v) { acc_aa[mt][nt][v] = 0; acc_m[mt][nt][v] = 0; }

    issue_chunk(0, 0);

    const int g8 = lane >> 3;     // ldmatrix group 0..3
    const int r8 = lane & 7;

    for (int ch = 0; ch < NCHK; ++ch) {
        if (ch + 1 < NCHK) {
            issue_chunk(ch + 1, (ch + 1) & 1);
            cp_wait<1>();
        } else {
            cp_wait<0>();
        }
        __syncthreads();

        const uint32_t stb = sbase + (ch & 1) * STAGEB;
        const uint32_t AaB = stb, AbB = stb + TILEB;
        const uint32_t BaB = stb + 2 * TILEB, BbB = stb + 3 * TILEB;

        uint32_t aA[2][4], aB[2][4], bR[4][4];

        // A fragments: matrices {rows0-7 k0-15, rows8-15 k0-15, rows0-7 k16-31, rows8-15 k16-31}
        // lane group g: row = R0 + r8 + (g&1)*8, half = g>>1
#pragma unroll
        for (int mt = 0; mt < 2; ++mt) {
            const int R0 = wm * 32 + mt * 16;
            const int arow = R0 + r8 + ((g8 & 1) << 3);
            const int ah = g8 >> 1;
            ldm4(aA[mt][0], aA[mt][1], aA[mt][2], aA[mt][3], qaddr(AaB, arow, ah));
            ldm4(aB[mt][0], aB[mt][1], aB[mt][2], aB[mt][3], qaddr(AbB, arow, ah));
        }
        // B fragments (Ba): matrices {n0-7 k0-15, n0-7 k16-31, n8-15 k0-15, n8-15 k16-31}
        // lane group g: row = N0 + r8 + (g>>1)*8, half = g&1
#pragma unroll
        for (int np = 0; np < 4; ++np) {
            const int N0 = wn * 64 + np * 16;
            const int brow = N0 + r8 + ((g8 >> 1) << 3);
            const int bh = g8 & 1;
            ldm4(bR[np][0], bR[np][1], bR[np][2], bR[np][3], qaddr(BaB, brow, bh));
        }
        // pass 1: aa -> acc_aa
#pragma unroll
        for (int mt = 0; mt < 2; ++mt)
#pragma unroll
            for (int nt = 0; nt < 8; ++nt)
                mma_s8(acc_aa[mt][nt], aA[mt],
                       bR[nt >> 1][(nt & 1) * 2], bR[nt >> 1][(nt & 1) * 2 + 1]);
        // pass 2: b*a -> acc_m  (Ab x Ba, reuses bR)
#pragma unroll
        for (int mt = 0; mt < 2; ++mt)
#pragma unroll
            for (int nt = 0; nt < 8; ++nt)
                mma_s8(acc_m[mt][nt], aB[mt],
                       bR[nt >> 1][(nt & 1) * 2], bR[nt >> 1][(nt & 1) * 2 + 1]);
        // load Bb over bR, pass 3: a*b -> acc_m
#pragma unroll
        for (int np = 0; np < 4; ++np) {
            const int N0 = wn * 64 + np * 16;
            const int brow = N0 + r8 + ((g8 >> 1) << 3);
            const int bh = g8 & 1;
            ldm4(bR[np][0], bR[np][1], bR[np][2], bR[np][3], qaddr(BbB, brow, bh));
        }
#pragma unroll
        for (int mt = 0; mt < 2; ++mt)
#pragma unroll
            for (int nt = 0; nt < 8; ++nt)
                mma_s8(acc_m[mt][nt], aA[mt],
                       bR[nt >> 1][(nt & 1) * 2], bR[nt >> 1][(nt & 1) * 2 + 1]);

        __syncthreads();   // stage consumed
    }

    // ---- epilogue ----
    const float sc = expf(t[0]);
    const float C1 = 1.0f / 256.0f;       // 1/s^2
    const float C2 = 1.0f / 65024.0f;     // 1/(254*s^2)
    const float* diag = &g_diag[b * Dc];
    float* outb = out + (size_t)b * TRIc;
    const bool diagBlk = (bi == bj);

    float colpart[16];
#pragma unroll
    for (int c = 0; c < 16; ++c) colpart[c] = 0.f;

#pragma unroll
    for (int mt = 0; mt < 2; ++mt) {
#pragma unroll
        for (int vr = 0; vr < 2; ++vr) {
            const int lr = wm * 32 + mt * 16 + (lane >> 2) + vr * 8;
            const int i = i0 + lr;
            const float di = diag[i];
            const int rowbase = (i * (2 * Dc - i + 1)) >> 1;
            float rowpart = 0.f;
#pragma unroll
            for (int nt = 0; nt < 8; ++nt) {
#pragma unroll
                for (int bb2 = 0; bb2 < 2; ++bb2) {
                    const int lc = wn * 64 + nt * 8 + ((lane & 3) << 1) + bb2;
                    const int j = j0 + lc;
                    if (diagBlk && j < i) continue;
                    float dv;
                    if (i == j) {
                        dv = 0.f;
                    } else {
                        const float gme =
                            (float)acc_aa[mt][nt][vr * 2 + bb2] * C1 +
                            (float)acc_m [mt][nt][vr * 2 + bb2] * C2;
                        dv = fmaxf(di + diag[j] - 2.f * gme, 0.f);
                    }
                    const float v = sqrtf(fmaf(sc, dv, 1e-5f));
                    outb[rowbase + (j - i)] = v;
                    rowpart += v;
                    if (j > i) colpart[nt * 2 + bb2] += v;
                }
            }
            atomicAdd(&rsum_i[lr], rowpart);
        }
    }
#pragma unroll
    for (int nt = 0; nt < 8; ++nt)
#pragma unroll
        for (int bb2 = 0; bb2 < 2; ++bb2) {
            const int lc = wn * 64 + nt * 8 + ((lane & 3) << 1) + bb2;
            atomicAdd(&rsum_j[lc], colpart[nt * 2 + bb2]);
        }
    __syncthreads();

    if (tid < TB) {
        atomicAdd(&g_rowsum[b * Dc + i0 + tid], rsum_i[tid]);
        atomicAdd(&g_rowsum[b * Dc + j0 + tid], rsum_j[tid]);
    }
}

// ---------------------------------------------------------------------------
// Kernel 4: in-place double centering; mirrored row pairs; float4 body.
// tot computed per-block from smem-staged rsn (fused).
// ---------------------------------------------------------------------------
__global__ void __launch_bounds__(256) center_kernel(float* __restrict__ out) {
    __shared__ float rsn[Dc];
    __shared__ float red[8];
    const int g = blockIdx.x;     // 0..63
    const int b = blockIdx.y;
    const float inv = 1.0f / (float)Dc;
    const float* rs = &g_rowsum[b * Dc];
#pragma unroll
    for (int u = 0; u < 2; ++u)
        rsn[threadIdx.x + u * 256] = rs[threadIdx.x + u * 256] * inv;
    __syncthreads();
    {
        float s = rsn[threadIdx.x] + rsn[threadIdx.x + 256];
#pragma unroll
        for (int o = 16; o > 0; o >>= 1) s += __shfl_down_sync(0xffffffffu, s, o);
        if ((threadIdx.x & 31) == 0) red[threadIdx.x >> 5] = s;
    }
    __syncthreads();
    float totm;
    {
        float tt = 0.f;
#pragma unroll
        for (int w = 0; w < 8; ++w) tt += red[w];
        totm = tt * inv;
    }
    float* outb = out + (size_t)b * TRIc;

#pragma unroll
    for (int u = 0; u < 4; ++u) {
        const int ia  = g * 4 + u;
        const int ib2 = (Dc - 1) - ia;
#pragma unroll
        for (int s = 0; s < 2; ++s) {
            const int i = s ? ib2 : ia;
            const float add = totm - rsn[i];
            const int rowbase = (i * (2 * Dc - i + 1)) >> 1;
            float* row = outb + rowbase;
            const int len = Dc - i;
            int start = (4 - (rowbase & 3)) & 3;
            if (start > len) start = len;
            if (threadIdx.x < (unsigned)start) {
                int jj = threadIdx.x;
                row[jj] += add - rsn[i + jj];
            }
            const int nv4 = (len - start) >> 2;
            float4* p4 = (float4*)(row + start);
            const float* rb = &rsn[i + start];
            for (int q = threadIdx.x; q < nv4; q += 256) {
                float4 v = p4[q];
                const int o4 = q * 4;
                v.x += add - rb[o4];
                v.y += add - rb[o4 + 1];
                v.z += add - rb[o4 + 2];
                v.w += add - rb[o4 + 3];
                p4[q] = v;
            }
            const int tail0 = start + nv4 * 4;
            for (int jj = tail0 + threadIdx.x; jj < len; jj += 256) {
                row[jj] += add - rsn[i + jj];
            }
        }
    }
}

// ---------------------------------------------------------------------------
extern "C" void kernel_launch(void* const* d_in, const int* in_sizes, int n_in,
                              void* d_out, int out_size) {
    const float* x = (const float*)d_in[0];
    const float* t = (const float*)d_in[1];
    if (n_in >= 2 && in_sizes[0] == 1) {
        x = (const float*)d_in[1];
        t = (const float*)d_in[0];
    }
    float* out = (float*)d_out;

    // gram_kernel kept as 4th launch (ncu capture slot)
    quant_kernel<<<dim3(KP / 16, Dc / 64, Bc), 256>>>(x);
    diag_kernel<<<Bc, 512>>>(x);
    zero_kernel<<<Bc, 512>>>();
    gram_kernel<<<dim3(NPAIR, Bc), 256>>>(t, out);
    center_kernel<<<dim3(64, Bc), 256>>>(out);
}

// round 14
// speedup vs baseline: 1.6275x; 1.6275x over previous
#include <cuda_runtime.h>
#include <cuda_bf16.h>
#include <math.h>
#include <stdint.h>

// Problem constants
#define Bc   256
#define Mc   196
#define Dc   512
#define TRIc 131328            // 512*513/2
#define KC   16                // K chunk rows (196 padded to 208 = 13*16)
#define NCH  13
#define PITCH_A 136            // A smem pitch in bf16 (272B)
#define PITCH_B 72             // B smem pitch in bf16 (144B)
#define TILEA (KC * PITCH_A * 2)   // 4352
#define TILEB2 (KC * PITCH_B * 2)  // 2304
#define STAGE (2 * TILEA + 2 * TILEB2)  // Ahi,Alo,Bhi,Blo = 13312
#define NST  3
#define NPAIR 10
#define NTILE 20               // 10 pairs x 2 column halves

// Scratch (allocation-free rule: __device__ globals)
__device__ float g_diag[Bc * Dc];
__device__ float g_rowsum[Bc * Dc];
__device__ __nv_bfloat16 g_xhi[(size_t)Bc * Mc * Dc];
__device__ __nv_bfloat16 g_xlo[(size_t)Bc * Mc * Dc];

__constant__ int c_bi[NPAIR] = {0,0,0,0,1,1,1,2,2,3};
__constant__ int c_bj[NPAIR] = {0,1,2,3,1,2,3,2,3,3};

// ---------------------------------------------------------------------------
// PTX helpers (base PTX only — sm_103-safe)
// ---------------------------------------------------------------------------
__device__ __forceinline__ void ldm4t(uint32_t& r0, uint32_t& r1, uint32_t& r2,
                                      uint32_t& r3, uint32_t addr) {
    asm volatile("ldmatrix.sync.aligned.m8n8.x4.trans.shared.b16 {%0,%1,%2,%3}, [%4];"
                 : "=r"(r0), "=r"(r1), "=r"(r2), "=r"(r3) : "r"(addr));
}

__device__ __forceinline__ void mma_bf16(float* d, const uint32_t* a, const uint32_t* b) {
    asm volatile(
        "mma.sync.aligned.m16n8k16.row.col.f32.bf16.bf16.f32 "
        "{%0,%1,%2,%3}, {%4,%5,%6,%7}, {%8,%9}, {%0,%1,%2,%3};"
        : "+f"(d[0]), "+f"(d[1]), "+f"(d[2]), "+f"(d[3])
        : "r"(a[0]), "r"(a[1]), "r"(a[2]), "r"(a[3]), "r"(b[0]), "r"(b[1]));
}

__device__ __forceinline__ void cp16(uint32_t saddr, const void* gaddr, uint32_t srcsz) {
    asm volatile("cp.async.ca.shared.global [%0], [%1], 16, %2;"
                 :: "r"(saddr), "l"(gaddr), "r"(srcsz) : "memory");
}
__device__ __forceinline__ void cp_commit() {
    asm volatile("cp.async.commit_group;" ::: "memory");
}
template<int N>
__device__ __forceinline__ void cp_wait() {
    asm volatile("cp.async.wait_group %0;" :: "n"(N) : "memory");
}

// Fragment base for a (0, c0) 16x16 block in a [k][col] bf16 tile of given pitch.
__device__ __forceinline__ uint32_t frag_addr(uint32_t base, int c0, int lane, int pitchB) {
    int g = lane >> 3, r = lane & 7;
    int k = r + ((g >> 1) << 3);
    int c = c0 + ((g & 1) << 3);
    return base + (uint32_t)(k * pitchB + c * 2);
}

// ---------------------------------------------------------------------------
// Kernel 0: fp32 -> bf16 hi/lo split (streamed once)
// ---------------------------------------------------------------------------
__global__ void __launch_bounds__(256) split_kernel(const float* __restrict__ x) {
    const size_t idx = (size_t)blockIdx.x * 256 + threadIdx.x;   // float4 index
    const float4 v = ((const float4*)x)[idx];
    __nv_bfloat16 h0 = __float2bfloat16(v.x), h1 = __float2bfloat16(v.y);
    __nv_bfloat16 h2 = __float2bfloat16(v.z), h3 = __float2bfloat16(v.w);
    __nv_bfloat162 hA(h0, h1), hB(h2, h3);
    __nv_bfloat162 lA(__float2bfloat16(v.x - __bfloat162float(h0)),
                      __float2bfloat16(v.y - __bfloat162float(h1)));
    __nv_bfloat162 lB(__float2bfloat16(v.z - __bfloat162float(h2)),
                      __float2bfloat16(v.w - __bfloat162float(h3)));
    uint2 uh, ul;
    uh.x = *(uint32_t*)&hA; uh.y = *(uint32_t*)&hB;
    ul.x = *(uint32_t*)&lA; ul.y = *(uint32_t*)&lB;
    *(uint2*)(g_xhi + idx * 4) = uh;
    *(uint2*)(g_xlo + idx * 4) = ul;
}

// ---------------------------------------------------------------------------
// Kernel 1: diag[b,d] = sum_m x[b,m,d]^2   (fp32, exact)
// ---------------------------------------------------------------------------
__global__ void __launch_bounds__(512) diag_kernel(const float* __restrict__ x) {
    int b = blockIdx.x;
    int d = threadIdx.x;
    const float* xb = x + (size_t)b * Mc * Dc + d;
    float s = 0.f;
#pragma unroll 4
    for (int m = 0; m < Mc; ++m) {
        float v = xb[(size_t)m * Dc];
        s = fmaf(v, v, s);
    }
    g_diag[b * Dc + d] = s;
}

// ---------------------------------------------------------------------------
// Kernel 2: zero g_rowsum
// ---------------------------------------------------------------------------
__global__ void __launch_bounds__(512) zero_kernel() {
    g_rowsum[blockIdx.x * 512 + threadIdx.x] = 0.f;
}

// ---------------------------------------------------------------------------
// Kernel 3: 128(M)x64(N) gram tile, bf16-split mma.sync, 3-stage cp.async.
// 256 threads = 8 warps; warp tile 32(M) x 32(N) -> 32 acc regs.
// STATIC smem: 3 stages x [Ahi|Alo|Bhi|Blo] = 39936 B + rsum.
// grid.x = 20: pair = x>>1, column half = x&1.
// ---------------------------------------------------------------------------
__global__ void __launch_bounds__(256, 3) gram_kernel(const float* __restrict__ t,
                                                      float* __restrict__ out) {
    __shared__ __align__(16) char smem[NST * STAGE];
    __shared__ float rsum_i[128];
    __shared__ float rsum_j[64];
    const uint32_t sbase = (uint32_t)__cvta_generic_to_shared(smem);

    const int b    = blockIdx.y;
    const int pair = blockIdx.x >> 1;
    const int half = blockIdx.x & 1;
    const int bi   = c_bi[pair];
    const int bj   = c_bj[pair];
    const int tid  = threadIdx.x;
    const int lane = tid & 31;
    const int wid  = tid >> 5;
    const int wm   = wid & 3;    // 4 M groups of 32 rows
    const int wn   = wid >> 2;   // 2 N groups of 32 cols

    const int i0 = bi * 128;
    const int j0 = bj * 128 + half * 64;
    const size_t rowbase_g = (size_t)b * Mc * Dc;

    // cp.async: 768 16B-chunks per stage over 256 threads (3 each)
    auto issue_chunk = [&](int ch, int st) {
        const uint32_t stb = sbase + st * STAGE;
        const int k0c = ch * KC;
#pragma unroll
        for (int it = 0; it < 3; ++it) {
            const int slot = tid + it * 256;     // 0..767
            if (slot < 512) {                    // A tiles: 16 rows x 16 c16 x 2
                const int tile = slot >> 8;      // 0=hi 1=lo
                const int r    = (slot >> 4) & 15;
                const int c16  = slot & 15;
                const int kg   = k0c + r;
                const int kcl  = (kg < Mc) ? kg : 0;
                const uint32_t srcsz = (kg < Mc) ? 16u : 0u;
                const __nv_bfloat16* src =
                    (tile ? g_xlo : g_xhi) + rowbase_g + (size_t)kcl * Dc + i0 + c16 * 8;
                cp16(stb + tile * TILEA + r * (PITCH_A * 2) + c16 * 16, src, srcsz);
            } else {                             // B tiles: 16 rows x 8 c16 x 2
                const int s2   = slot - 512;
                const int tile = s2 >> 7;
                const int inner = s2 & 127;
                const int r    = inner >> 3;
                const int c16  = inner & 7;
                const int kg   = k0c + r;
                const int kcl  = (kg < Mc) ? kg : 0;
                const uint32_t srcsz = (kg < Mc) ? 16u : 0u;
                const __nv_bfloat16* src =
                    (tile ? g_xlo : g_xhi) + rowbase_g + (size_t)kcl * Dc + j0 + c16 * 8;
                cp16(stb + 2 * TILEA + tile * TILEB2 + r * (PITCH_B * 2) + c16 * 16,
                     src, srcsz);
            }
        }
        cp_commit();
    };

    if (tid < 128) rsum_i[tid] = 0.f;
    if (tid < 64)  rsum_j[tid] = 0.f;

    float acc[2][4][4];
#pragma unroll
    for (int mt = 0; mt < 2; ++mt)
#pragma unroll
        for (int nt = 0; nt < 4; ++nt)
#pragma unroll
            for (int v = 0; v < 4; ++v) acc[mt][nt][v] = 0.f;

    issue_chunk(0, 0);
    issue_chunk(1, 1);

    for (int ch = 0; ch < NCH; ++ch) {
        if (ch + 2 < NCH) {
            issue_chunk(ch + 2, (ch + 2) % NST);
            cp_wait<2>();
        } else if (ch + 1 < NCH) {
            cp_wait<1>();
        } else {
            cp_wait<0>();
        }
        __syncthreads();

        const uint32_t stb = sbase + (ch % NST) * STAGE;
        const uint32_t aHiB = stb, aLoB = stb + TILEA;
        const uint32_t bHiB = stb + 2 * TILEA, bLoB = bHiB + TILEB2;

        uint32_t aHi[2][4], aLo[2][4], bF[2][4];
        // A fragments (hi kept register-resident for pass 3)
#pragma unroll
        for (int mt = 0; mt < 2; ++mt) {
            ldm4t(aHi[mt][0], aHi[mt][1], aHi[mt][2], aHi[mt][3],
                  frag_addr(aHiB, wm * 32 + mt * 16, lane, PITCH_A * 2));
            ldm4t(aLo[mt][0], aLo[mt][1], aLo[mt][2], aLo[mt][3],
                  frag_addr(aLoB, wm * 32 + mt * 16, lane, PITCH_A * 2));
        }
        // pass 1: hi * hi
#pragma unroll
        for (int np = 0; np < 2; ++np)
            ldm4t(bF[np][0], bF[np][1], bF[np][2], bF[np][3],
                  frag_addr(bHiB, wn * 32 + np * 16, lane, PITCH_B * 2));
#pragma unroll
        for (int mt = 0; mt < 2; ++mt)
#pragma unroll
            for (int nt = 0; nt < 4; ++nt) {
                uint32_t bb[2] = { bF[nt >> 1][nt & 1], bF[nt >> 1][2 + (nt & 1)] };
                mma_bf16(acc[mt][nt], aHi[mt], bb);
            }
        // pass 2: lo * hi
#pragma unroll
        for (int mt = 0; mt < 2; ++mt)
#pragma unroll
            for (int nt = 0; nt < 4; ++nt) {
                uint32_t bb[2] = { bF[nt >> 1][nt & 1], bF[nt >> 1][2 + (nt & 1)] };
                mma_bf16(acc[mt][nt], aLo[mt], bb);
            }
        // pass 3: hi * lo
#pragma unroll
        for (int np = 0; np < 2; ++np)
            ldm4t(bF[np][0], bF[np][1], bF[np][2], bF[np][3],
                  frag_addr(bLoB, wn * 32 + np * 16, lane, PITCH_B * 2));
#pragma unroll
        for (int mt = 0; mt < 2; ++mt)
#pragma unroll
            for (int nt = 0; nt < 4; ++nt) {
                uint32_t bb[2] = { bF[nt >> 1][nt & 1], bF[nt >> 1][2 + (nt & 1)] };
                mma_bf16(acc[mt][nt], aHi[mt], bb);
            }

        __syncthreads();   // stage consumed
    }

    // ---- epilogue ----
    const float sc = expf(t[0]);
    const float* diag = &g_diag[b * Dc];
    float* outb = out + (size_t)b * TRIc;
    const bool diagBlk = (bi == bj);

    float colpart[8];
#pragma unroll
    for (int c = 0; c < 8; ++c) colpart[c] = 0.f;

#pragma unroll
    for (int mt = 0; mt < 2; ++mt) {
#pragma unroll
        for (int vr = 0; vr < 2; ++vr) {
            const int lr = wm * 32 + mt * 16 + (lane >> 2) + vr * 8;
            const int i = i0 + lr;
            const float di = diag[i];
            const int rowbase = (i * (2 * Dc - i + 1)) >> 1;
            float rowpart = 0.f;
#pragma unroll
            for (int nt = 0; nt < 4; ++nt) {
#pragma unroll
                for (int bb2 = 0; bb2 < 2; ++bb2) {
                    const int lc = wn * 32 + nt * 8 + ((lane & 3) << 1) + bb2;
                    const int j = j0 + lc;
                    if (diagBlk && j < i) continue;
                    float dv;
                    if (i == j) {
                        dv = 0.f;
                    } else {
                        dv = di + diag[j] - 2.f * acc[mt][nt][vr * 2 + bb2];
                        dv = fmaxf(dv, 0.f);
                    }
                    const float v = sqrtf(fmaf(sc, dv, 1e-5f));
                    outb[rowbase + (j - i)] = v;
                    rowpart += v;
                    if (j > i) colpart[nt * 2 + bb2] += v;
                }
            }
            atomicAdd(&rsum_i[lr], rowpart);
        }
    }
#pragma unroll
    for (int nt = 0; nt < 4; ++nt)
#pragma unroll
        for (int bb2 = 0; bb2 < 2; ++bb2) {
            const int lc = wn * 32 + nt * 8 + ((lane & 3) << 1) + bb2;
            atomicAdd(&rsum_j[lc], colpart[nt * 2 + bb2]);
        }
    __syncthreads();

    if (tid < 128) atomicAdd(&g_rowsum[b * Dc + i0 + tid], rsum_i[tid]);
    if (tid < 64)  atomicAdd(&g_rowsum[b * Dc + j0 + tid], rsum_j[tid]);
}

// ---------------------------------------------------------------------------
// Kernel 4: in-place double centering; mirrored row pairs; float4 body.
// tot computed per-block from smem-staged rsn (fused).
// ---------------------------------------------------------------------------
__global__ void __launch_bounds__(256) center_kernel(float* __restrict__ out) {
    __shared__ float rsn[Dc];
    __shared__ float red[8];
    const int g = blockIdx.x;     // 0..63
    const int b = blockIdx.y;
    const float inv = 1.0f / (float)Dc;
    const float* rs = &g_rowsum[b * Dc];
#pragma unroll
    for (int u = 0; u < 2; ++u)
        rsn[threadIdx.x + u * 256] = rs[threadIdx.x + u * 256] * inv;
    __syncthreads();
    {
        float s = rsn[threadIdx.x] + rsn[threadIdx.x + 256];
#pragma unroll
        for (int o = 16; o > 0; o >>= 1) s += __shfl_down_sync(0xffffffffu, s, o);
        if ((threadIdx.x & 31) == 0) red[threadIdx.x >> 5] = s;
    }
    __syncthreads();
    float totm;
    {
        float tt = 0.f;
#pragma unroll
        for (int w = 0; w < 8; ++w) tt += red[w];
        totm = tt * inv;
    }
    float* outb = out + (size_t)b * TRIc;

#pragma unroll
    for (int u = 0; u < 4; ++u) {
        const int ia  = g * 4 + u;
        const int ib2 = (Dc - 1) - ia;
#pragma unroll
        for (int s = 0; s < 2; ++s) {
            const int i = s ? ib2 : ia;
            const float add = totm - rsn[i];
            const int rowbase = (i * (2 * Dc - i + 1)) >> 1;
            float* row = outb + rowbase;
            const int len = Dc - i;
            int start = (4 - (rowbase & 3)) & 3;
            if (start > len) start = len;
            if (threadIdx.x < (unsigned)start) {
                int jj = threadIdx.x;
                row[jj] += add - rsn[i + jj];
            }
            const int nv4 = (len - start) >> 2;
            float4* p4 = (float4*)(row + start);
            const float* rb = &rsn[i + start];
            for (int q = threadIdx.x; q < nv4; q += 256) {
                float4 v = p4[q];
                const int o4 = q * 4;
                v.x += add - rb[o4];
                v.y += add - rb[o4 + 1];
                v.z += add - rb[o4 + 2];
                v.w += add - rb[o4 + 3];
                p4[q] = v;
            }
            const int tail0 = start + nv4 * 4;
            for (int jj = tail0 + threadIdx.x; jj < len; jj += 256) {
                row[jj] += add - rsn[i + jj];
            }
        }
    }
}

// ---------------------------------------------------------------------------
extern "C" void kernel_launch(void* const* d_in, const int* in_sizes, int n_in,
                              void* d_out, int out_size) {
    const float* x = (const float*)d_in[0];
    const float* t = (const float*)d_in[1];
    if (n_in >= 2 && in_sizes[0] == 1) {
        x = (const float*)d_in[1];
        t = (const float*)d_in[0];
    }
    float* out = (float*)d_out;

    // gram_kernel kept as 4th launch (ncu capture slot)
    split_kernel<<<(Bc * Mc * Dc) / (256 * 4), 256>>>(x);
    diag_kernel<<<Bc, 512>>>(x);
    zero_kernel<<<Bc, 512>>>();
    gram_kernel<<<dim3(NTILE, Bc), 256>>>(t, out);
    center_kernel<<<dim3(64, Bc), 256>>>(out);
}

// round 17
// speedup vs baseline: 1.8921x; 1.1626x over previous
#include <cuda_runtime.h>
#include <cuda_fp16.h>
#include <math.h>
#include <stdint.h>

// Problem constants
#define Bc   256
#define Mc   196
#define Dc   512
#define TRIc 131328            // 512*513/2
#define KC   16                // K chunk rows (196 padded to 208 = 13*16)
#define NCH  13
#define PITCH_A 136            // A smem pitch in fp16 (272B)
#define PITCH_B 72             // B smem pitch in fp16 (144B)
#define TILEA (KC * PITCH_A * 2)   // 4352
#define TILEB2 (KC * PITCH_B * 2)  // 2304
#define STAGE (TILEA + TILEB2)     // A|B = 6656
#define NST  4
#define NPAIR 10
#define NTILE 20               // 10 pairs x 2 column halves

// Scratch (allocation-free rule: __device__ globals)
__device__ float  g_diag[Bc * Dc];
__device__ float  g_rowsum[Bc * Dc];
__device__ __half g_xh[(size_t)Bc * Mc * Dc];

__constant__ int c_bi[NPAIR] = {0,0,0,0,1,1,1,2,2,3};
__constant__ int c_bj[NPAIR] = {0,1,2,3,1,2,3,2,3,3};

// ---------------------------------------------------------------------------
// PTX helpers (base PTX only — sm_103-safe)
// ---------------------------------------------------------------------------
__device__ __forceinline__ void ldm4t(uint32_t& r0, uint32_t& r1, uint32_t& r2,
                                      uint32_t& r3, uint32_t addr) {
    asm volatile("ldmatrix.sync.aligned.m8n8.x4.trans.shared.b16 {%0,%1,%2,%3}, [%4];"
                 : "=r"(r0), "=r"(r1), "=r"(r2), "=r"(r3) : "r"(addr));
}

__device__ __forceinline__ void mma_f16(float* d, const uint32_t* a, const uint32_t* b) {
    asm volatile(
        "mma.sync.aligned.m16n8k16.row.col.f32.f16.f16.f32 "
        "{%0,%1,%2,%3}, {%4,%5,%6,%7}, {%8,%9}, {%0,%1,%2,%3};"
        : "+f"(d[0]), "+f"(d[1]), "+f"(d[2]), "+f"(d[3])
        : "r"(a[0]), "r"(a[1]), "r"(a[2]), "r"(a[3]), "r"(b[0]), "r"(b[1]));
}

__device__ __forceinline__ void cp16(uint32_t saddr, const void* gaddr, uint32_t srcsz) {
    asm volatile("cp.async.ca.shared.global [%0], [%1], 16, %2;"
                 :: "r"(saddr), "l"(gaddr), "r"(srcsz) : "memory");
}
__device__ __forceinline__ void cp_commit() {
    asm volatile("cp.async.commit_group;" ::: "memory");
}
template<int N>
__device__ __forceinline__ void cp_wait() {
    asm volatile("cp.async.wait_group %0;" :: "n"(N) : "memory");
}

// Fragment base for a (0, c0) 16x16 block in a [k][col] fp16 tile of given pitch.
__device__ __forceinline__ uint32_t frag_addr(uint32_t base, int c0, int lane, int pitchB) {
    int g = lane >> 3, r = lane & 7;
    int k = r + ((g >> 1) << 3);
    int c = c0 + ((g & 1) << 3);
    return base + (uint32_t)(k * pitchB + c * 2);
}

// ---------------------------------------------------------------------------
// Kernel 0: fp32 -> fp16 quantize (streamed once).  Consistent-quantization:
// gram AND diag both computed from this same x-hat.
// ---------------------------------------------------------------------------
__global__ void __launch_bounds__(256) split_kernel(const float* __restrict__ x) {
    const size_t idx = (size_t)blockIdx.x * 256 + threadIdx.x;   // float4 index
    const float4 v = ((const float4*)x)[idx];
    __half2 h01 = __floats2half2_rn(v.x, v.y);
    __half2 h23 = __floats2half2_rn(v.z, v.w);
    uint2 u;
    u.x = *(uint32_t*)&h01;
    u.y = *(uint32_t*)&h23;
    *(uint2*)(g_xh + idx * 4) = u;
}

// ---------------------------------------------------------------------------
// Kernel 1: diag[b,d] = sum_m xhat[b,m,d]^2  (fp32 accum over fp16 values —
// consistent with the gram computed from the same xhat)
// ---------------------------------------------------------------------------
__global__ void __launch_bounds__(512) diag_kernel() {
    int b = blockIdx.x;
    int d = threadIdx.x;
    const __half* xb = g_xh + (size_t)b * Mc * Dc + d;
    float s = 0.f;
#pragma unroll 4
    for (int m = 0; m < Mc; ++m) {
        float v = __half2float(xb[(size_t)m * Dc]);
        s = fmaf(v, v, s);
    }
    g_diag[b * Dc + d] = s;
}

// ---------------------------------------------------------------------------
// Kernel 2: zero g_rowsum
// ---------------------------------------------------------------------------
__global__ void __launch_bounds__(512) zero_kernel() {
    g_rowsum[blockIdx.x * 512 + threadIdx.x] = 0.f;
}

// ---------------------------------------------------------------------------
// Kernel 3: 128(M)x64(N) gram tile, single-pass fp16 mma.sync, 4-stage
// cp.async pipeline with ONE barrier per chunk (issue distance 2 of 4 stages).
// 256 threads = 8 warps; warp tile 32(M) x 32(N) -> 32 acc regs.
// STATIC smem: 4 stages x [A|B] = 26624 B + rsum.
// grid.x = 20: pair = x>>1, column half = x&1.
// ---------------------------------------------------------------------------
__global__ void __launch_bounds__(256, 3) gram_kernel(const float* __restrict__ t,
                                                      float* __restrict__ out) {
    __shared__ __align__(16) char smem[NST * STAGE];
    __shared__ float rsum_i[128];
    __shared__ float rsum_j[64];
    const uint32_t sbase = (uint32_t)__cvta_generic_to_shared(smem);

    const int b    = blockIdx.y;
    const int pair = blockIdx.x >> 1;
    const int half = blockIdx.x & 1;
    const int bi   = c_bi[pair];
    const int bj   = c_bj[pair];
    const int tid  = threadIdx.x;
    const int lane = tid & 31;
    const int wid  = tid >> 5;
    const int wm   = wid & 3;    // 4 M groups of 32 rows
    const int wn   = wid >> 2;   // 2 N groups of 32 cols

    const int i0 = bi * 128;
    const int j0 = bj * 128 + half * 64;
    const size_t rowbase_g = (size_t)b * Mc * Dc;

    // cp.async: 384 16B-chunks per stage over 256 threads (A:256, B:128)
    auto issue_chunk = [&](int ch, int st) {
        const uint32_t stb = sbase + st * STAGE;
        const int k0c = ch * KC;
#pragma unroll
        for (int it = 0; it < 2; ++it) {
            const int slot = tid + it * 256;     // 0..511, skip >=384
            if (slot < 256) {                    // A: 16 rows x 16 c16
                const int r   = slot >> 4;
                const int c16 = slot & 15;
                const int kg  = k0c + r;
                const int kcl = (kg < Mc) ? kg : 0;
                const uint32_t srcsz = (kg < Mc) ? 16u : 0u;
                const __half* src = g_xh + rowbase_g + (size_t)kcl * Dc + i0 + c16 * 8;
                cp16(stb + r * (PITCH_A * 2) + c16 * 16, src, srcsz);
            } else if (slot < 384) {             // B: 16 rows x 8 c16
                const int s2  = slot - 256;
                const int r   = s2 >> 3;
                const int c16 = s2 & 7;
                const int kg  = k0c + r;
                const int kcl = (kg < Mc) ? kg : 0;
                const uint32_t srcsz = (kg < Mc) ? 16u : 0u;
                const __half* src = g_xh + rowbase_g + (size_t)kcl * Dc + j0 + c16 * 8;
                cp16(stb + TILEA + r * (PITCH_B * 2) + c16 * 16, src, srcsz);
            }
        }
        cp_commit();
    };

    if (tid < 128) rsum_i[tid] = 0.f;
    if (tid < 64)  rsum_j[tid] = 0.f;

    float acc[2][4][4];
#pragma unroll
    for (int mt = 0; mt < 2; ++mt)
#pragma unroll
        for (int nt = 0; nt < 4; ++nt)
#pragma unroll
            for (int v = 0; v < 4; ++v) acc[mt][nt][v] = 0.f;

    issue_chunk(0, 0);
    issue_chunk(1, 1);

    for (int ch = 0; ch < NCH; ++ch) {
        if (ch + 2 < NCH) {
            issue_chunk(ch + 2, (ch + 2) % NST);
            cp_wait<2>();
        } else if (ch + 1 < NCH) {
            cp_wait<1>();
        } else {
            cp_wait<0>();
        }
        __syncthreads();     // single barrier per chunk (4-stage, distance-2)

        const uint32_t stb = sbase + (ch % NST) * STAGE;
        const uint32_t aB = stb, bB = stb + TILEA;

        uint32_t aF[2][4], bF[2][4];
#pragma unroll
        for (int mt = 0; mt < 2; ++mt)
            ldm4t(aF[mt][0], aF[mt][1], aF[mt][2], aF[mt][3],
                  frag_addr(aB, wm * 32 + mt * 16, lane, PITCH_A * 2));
#pragma unroll
        for (int np = 0; np < 2; ++np)
            ldm4t(bF[np][0], bF[np][1], bF[np][2], bF[np][3],
                  frag_addr(bB, wn * 32 + np * 16, lane, PITCH_B * 2));
#pragma unroll
        for (int mt = 0; mt < 2; ++mt)
#pragma unroll
            for (int nt = 0; nt < 4; ++nt) {
                uint32_t bb[2] = { bF[nt >> 1][nt & 1], bF[nt >> 1][2 + (nt & 1)] };
                mma_f16(acc[mt][nt], aF[mt], bb);
            }
    }

    // ---- epilogue ----
    const float sc = expf(t[0]);
    const float* diag = &g_diag[b * Dc];
    float* outb = out + (size_t)b * TRIc;
    const bool diagBlk = (bi == bj);

    float colpart[8];
#pragma unroll
    for (int c = 0; c < 8; ++c) colpart[c] = 0.f;

#pragma unroll
    for (int mt = 0; mt < 2; ++mt) {
#pragma unroll
        for (int vr = 0; vr < 2; ++vr) {
            const int lr = wm * 32 + mt * 16 + (lane >> 2) + vr * 8;
            const int i = i0 + lr;
            const float di = diag[i];
            const int rowbase = (i * (2 * Dc - i + 1)) >> 1;
            float rowpart = 0.f;
#pragma unroll
            for (int nt = 0; nt < 4; ++nt) {
#pragma unroll
                for (int bb2 = 0; bb2 < 2; ++bb2) {
                    const int lc = wn * 32 + nt * 8 + ((lane & 3) << 1) + bb2;
                    const int j = j0 + lc;
                    if (diagBlk && j < i) continue;
                    float dv;
                    if (i == j) {
                        dv = 0.f;
                    } else {
                        dv = di + diag[j] - 2.f * acc[mt][nt][vr * 2 + bb2];
                        dv = fmaxf(dv, 0.f);
                    }
                    const float v = sqrtf(fmaf(sc, dv, 1e-5f));
                    outb[rowbase + (j - i)] = v;
                    rowpart += v;
                    if (j > i) colpart[nt * 2 + bb2] += v;
                }
            }
            atomicAdd(&rsum_i[lr], rowpart);
        }
    }
#pragma unroll
    for (int nt = 0; nt < 4; ++nt)
#pragma unroll
        for (int bb2 = 0; bb2 < 2; ++bb2) {
            const int lc = wn * 32 + nt * 8 + ((lane & 3) << 1) + bb2;
            atomicAdd(&rsum_j[lc], colpart[nt * 2 + bb2]);
        }
    __syncthreads();

    if (tid < 128) atomicAdd(&g_rowsum[b * Dc + i0 + tid], rsum_i[tid]);
    if (tid < 64)  atomicAdd(&g_rowsum[b * Dc + j0 + tid], rsum_j[tid]);
}

// ---------------------------------------------------------------------------
// Kernel 4: in-place double centering; mirrored row pairs; float4 body.
// tot computed per-block from smem-staged rsn (fused).
// ---------------------------------------------------------------------------
__global__ void __launch_bounds__(256) center_kernel(float* __restrict__ out) {
    __shared__ float rsn[Dc];
    __shared__ float red[8];
    const int g = blockIdx.x;     // 0..63
    const int b = blockIdx.y;
    const float inv = 1.0f / (float)Dc;
    const float* rs = &g_rowsum[b * Dc];
#pragma unroll
    for (int u = 0; u < 2; ++u)
        rsn[threadIdx.x + u * 256] = rs[threadIdx.x + u * 256] * inv;
    __syncthreads();
    {
        float s = rsn[threadIdx.x] + rsn[threadIdx.x + 256];
#pragma unroll
        for (int o = 16; o > 0; o >>= 1) s += __shfl_down_sync(0xffffffffu, s, o);
        if ((threadIdx.x & 31) == 0) red[threadIdx.x >> 5] = s;
    }
    __syncthreads();
    float totm;
    {
        float tt = 0.f;
#pragma unroll
        for (int w = 0; w < 8; ++w) tt += red[w];
        totm = tt * inv;
    }
    float* outb = out + (size_t)b * TRIc;

#pragma unroll
    for (int u = 0; u < 4; ++u) {
        const int ia  = g * 4 + u;
        const int ib2 = (Dc - 1) - ia;
#pragma unroll
        for (int s = 0; s < 2; ++s) {
            const int i = s ? ib2 : ia;
            const float add = totm - rsn[i];
            const int rowbase = (i * (2 * Dc - i + 1)) >> 1;
            float* row = outb + rowbase;
            const int len = Dc - i;
            int start = (4 - (rowbase & 3)) & 3;
            if (start > len) start = len;
            if (threadIdx.x < (unsigned)start) {
                int jj = threadIdx.x;
                row[jj] += add - rsn[i + jj];
            }
            const int nv4 = (len - start) >> 2;
            float4* p4 = (float4*)(row + start);
            const float* rb = &rsn[i + start];
            for (int q = threadIdx.x; q < nv4; q += 256) {
                float4 v = p4[q];
                const int o4 = q * 4;
                v.x += add - rb[o4];
                v.y += add - rb[o4 + 1];
                v.z += add - rb[o4 + 2];
                v.w += add - rb[o4 + 3];
                p4[q] = v;
            }
            const int tail0 = start + nv4 * 4;
            for (int jj = tail0 + threadIdx.x; jj < len; jj += 256) {
                row[jj] += add - rsn[i + jj];
            }
        }
    }
}

// ---------------------------------------------------------------------------
extern "C" void kernel_launch(void* const* d_in, const int* in_sizes, int n_in,
                              void* d_out, int out_size) {
    const float* x = (const float*)d_in[0];
    const float* t = (const float*)d_in[1];
    if (n_in >= 2 && in_sizes[0] == 1) {
        x = (const float*)d_in[1];
        t = (const float*)d_in[0];
    }
    float* out = (float*)d_out;

    // gram_kernel kept as 4th launch (ncu capture slot)
    split_kernel<<<(Bc * Mc * Dc) / (256 * 4), 256>>>(x);
    diag_kernel<<<Bc, 512>>>();
    zero_kernel<<<Bc, 512>>>();
    gram_kernel<<<dim3(NTILE, Bc), 256>>>(t, out);
    center_kernel<<<dim3(64, Bc), 256>>>(out);
}